// round 15
// baseline (speedup 1.0000x reference)
#include <cuda_runtime.h>

// FCOS head decode: 32 x 128 x 128 pixels, 80 classes.
// Inputs (metadata order):
//   d_in[0] t_ltrb        [32,128,128,4]  f32
//   d_in[1] center_logits [32,128,128,1]  f32
//   d_in[2] cls_logits    [32,128,128,80] f32
//   d_in[3] img_h (unused), d_in[4] img_w (unused)
// Output (f32, concatenated in reference return order):
//   [0       , 2097152) : p_xywh flat
//   [2097152 , 2621440) : cls_idx as float
//   [2621440 , 3145728) : confs
//
// Structure identical to the R9..R13 optimum (29.5us kernel @ TPB=512,
// DRAM 80.3%): quad-per-pixel, direct global loads, front-batched epilogue
// loads, reduce-then-epilogue ordering. This round probes TPB=1024 (same
// per-thread SASS, same occupancy limit) for CTA-scheduling variance only.

#define NB   32
#define NH   128
#define NW   128
#define NCLS 80
#define HW   (NH * NW)
#define NPIX (NB * HW)          // 524288
#define STRIDE_F 8.0f

#define TPB   1024              // threads per block; 4 threads (a quad) per pixel
#define F4PP  (NCLS / 4)        // 20 float4 per pixel
#define RPT   (F4PP / 4)        // 5 float4 per thread

__global__ __launch_bounds__(TPB)
void fcos_decode_kernel(const float* __restrict__ t_ltrb,
                        const float* __restrict__ center,
                        const float* __restrict__ cls,
                        float* __restrict__ out)
{
    const int gtid = blockIdx.x * TPB + threadIdx.x;
    const int pix  = gtid >> 2;              // pixel id
    const int q    = gtid & 3;               // quad lane
    const long long gp = pix;

    // ---- front batch: 5 cls LDG.128 per thread, plus (q==0 only, predicated)
    //      the epilogue's t_ltrb float4 and center scalar -> MLP up to 7,
    //      removing two serialized DRAM latencies from the warp tail.
    const float4* __restrict__ c4 =
        reinterpret_cast<const float4*>(cls) + (long long)pix * F4PP + q;
    float4 v[RPT];
    #pragma unroll
    for (int r = 0; r < RPT; r++) v[r] = c4[r * 4];

    float4 t   = make_float4(0.f, 0.f, 0.f, 0.f);
    float  cen = 0.f;
    if (q == 0) {
        t   = *reinterpret_cast<const float4*>(t_ltrb + gp * 4);
        cen = center[gp];
    }

    // ---- per-thread max+argmax (class indices increasing -> '>' keeps first) ----
    float m  = -__int_as_float(0x7f800000);  // -inf
    int   mi = 0;
    #pragma unroll
    for (int r = 0; r < RPT; r++) {
        int b = (q + r * 4) * 4;             // global class index of v[r].x
        if (v[r].x > m) { m = v[r].x; mi = b;     }
        if (v[r].y > m) { m = v[r].y; mi = b + 1; }
        if (v[r].z > m) { m = v[r].z; mi = b + 2; }
        if (v[r].w > m) { m = v[r].w; mi = b + 3; }
    }

    // ---- intra-quad reduce, first-index tie-break (matches jnp.argmax) ----
    #pragma unroll
    for (int off = 1; off <= 2; off <<= 1) {
        float ov = __shfl_xor_sync(0xffffffffu, m,  off);
        int   oi = __shfl_xor_sync(0xffffffffu, mi, off);
        if (ov > m || (ov == m && oi < mi)) { m = ov; mi = oi; }
    }

    if (q == 0) {
        // ltrb decode: p = exp(t) * stride
        float pl = __expf(t.x) * STRIDE_F;
        float pt = __expf(t.y) * STRIDE_F;
        float pr = __expf(t.z) * STRIDE_F;
        float pb = __expf(t.w) * STRIDE_F;

        int hw = pix & (HW - 1);
        int hy = hw >> 7;                    // NW = 128
        int wx = hw & (NW - 1);
        float cx0 = (float)wx * STRIDE_F + STRIDE_F * 0.5f;
        float cy0 = (float)hy * STRIDE_F + STRIDE_F * 0.5f;

        float4 o;
        o.x = cx0 + (pr - pl) * 0.5f;        // cx
        o.y = cy0 + (pb - pt) * 0.5f;        // cy
        o.z = pl + pr;                       // w
        o.w = pt + pb;                       // h
        *reinterpret_cast<float4*>(out + gp * 4) = o;

        // conf = sqrt(sigmoid(center) * sigmoid(max_logit))  (sigmoid monotone)
        float pc = 1.0f / (1.0f + __expf(-cen));
        float ps = 1.0f / (1.0f + __expf(-m));

        out[(long long)NPIX * 4 + gp] = (float)mi;
        out[(long long)NPIX * 5 + gp] = sqrtf(pc * ps);
    }
}

extern "C" void kernel_launch(void* const* d_in, const int* in_sizes, int n_in,
                              void* d_out, int out_size)
{
    const float* t_ltrb = (const float*)d_in[0];
    const float* center = (const float*)d_in[1];
    const float* cls    = (const float*)d_in[2];
    float* out = (float*)d_out;

    const int total_threads = NPIX * 4;      // 4 threads per pixel
    fcos_decode_kernel<<<total_threads / TPB, TPB>>>(t_ltrb, center, cls, out);
}

// round 17
// speedup vs baseline: 1.0106x; 1.0106x over previous
#include <cuda_runtime.h>

// FCOS head decode: 32 x 128 x 128 pixels, 80 classes.
// Inputs (metadata order):
//   d_in[0] t_ltrb        [32,128,128,4]  f32
//   d_in[1] center_logits [32,128,128,1]  f32
//   d_in[2] cls_logits    [32,128,128,80] f32
//   d_in[3] img_h (unused), d_in[4] img_w (unused)
// Output (f32, concatenated in reference return order):
//   [0       , 2097152) : p_xywh flat
//   [2097152 , 2621440) : cls_idx as float
//   [2621440 , 3145728) : confs
//
// FINAL (best measured: 29.5us kernel, DRAM 80.3% = 6.35 TB/s, byte-minimal
// 191 MB traffic). Design: quad-per-pixel (4 threads/pixel) direct-global
// loads — warp request = 8 pixels x 64B windows -> 8 distinct 128B lines,
// sector-exact at DRAM; front-batched epilogue loads (t_ltrb/center hoisted
// above the reduction, predicated to q==0) -> MLP 7, no serialized tail;
// reduce-then-epilogue ordering (reordering regressed 23%); sigmoid
// monotonicity folds max(sigmoid(cls)) -> sigmoid(max(logits)); TPB=512
// optimal in {256,512,1024} sweep.

#define NB   32
#define NH   128
#define NW   128
#define NCLS 80
#define HW   (NH * NW)
#define NPIX (NB * HW)          // 524288
#define STRIDE_F 8.0f

#define TPB   512               // threads per block; 4 threads (a quad) per pixel
#define F4PP  (NCLS / 4)        // 20 float4 per pixel
#define RPT   (F4PP / 4)        // 5 float4 per thread

__global__ __launch_bounds__(TPB)
void fcos_decode_kernel(const float* __restrict__ t_ltrb,
                        const float* __restrict__ center,
                        const float* __restrict__ cls,
                        float* __restrict__ out)
{
    const int gtid = blockIdx.x * TPB + threadIdx.x;
    const int pix  = gtid >> 2;              // pixel id
    const int q    = gtid & 3;               // quad lane
    const long long gp = pix;

    // ---- front batch: 5 cls LDG.128 per thread, plus (q==0 only, predicated)
    //      the epilogue's t_ltrb float4 and center scalar -> MLP up to 7,
    //      removing two serialized DRAM latencies from the warp tail.
    const float4* __restrict__ c4 =
        reinterpret_cast<const float4*>(cls) + (long long)pix * F4PP + q;
    float4 v[RPT];
    #pragma unroll
    for (int r = 0; r < RPT; r++) v[r] = c4[r * 4];

    float4 t   = make_float4(0.f, 0.f, 0.f, 0.f);
    float  cen = 0.f;
    if (q == 0) {
        t   = *reinterpret_cast<const float4*>(t_ltrb + gp * 4);
        cen = center[gp];
    }

    // ---- per-thread max+argmax (class indices increasing -> '>' keeps first) ----
    float m  = -__int_as_float(0x7f800000);  // -inf
    int   mi = 0;
    #pragma unroll
    for (int r = 0; r < RPT; r++) {
        int b = (q + r * 4) * 4;             // global class index of v[r].x
        if (v[r].x > m) { m = v[r].x; mi = b;     }
        if (v[r].y > m) { m = v[r].y; mi = b + 1; }
        if (v[r].z > m) { m = v[r].z; mi = b + 2; }
        if (v[r].w > m) { m = v[r].w; mi = b + 3; }
    }

    // ---- intra-quad reduce, first-index tie-break (matches jnp.argmax) ----
    #pragma unroll
    for (int off = 1; off <= 2; off <<= 1) {
        float ov = __shfl_xor_sync(0xffffffffu, m,  off);
        int   oi = __shfl_xor_sync(0xffffffffu, mi, off);
        if (ov > m || (ov == m && oi < mi)) { m = ov; mi = oi; }
    }

    if (q == 0) {
        // ltrb decode: p = exp(t) * stride
        float pl = __expf(t.x) * STRIDE_F;
        float pt = __expf(t.y) * STRIDE_F;
        float pr = __expf(t.z) * STRIDE_F;
        float pb = __expf(t.w) * STRIDE_F;

        int hw = pix & (HW - 1);
        int hy = hw >> 7;                    // NW = 128
        int wx = hw & (NW - 1);
        float cx0 = (float)wx * STRIDE_F + STRIDE_F * 0.5f;
        float cy0 = (float)hy * STRIDE_F + STRIDE_F * 0.5f;

        float4 o;
        o.x = cx0 + (pr - pl) * 0.5f;        // cx
        o.y = cy0 + (pb - pt) * 0.5f;        // cy
        o.z = pl + pr;                       // w
        o.w = pt + pb;                       // h
        *reinterpret_cast<float4*>(out + gp * 4) = o;

        // conf = sqrt(sigmoid(center) * sigmoid(max_logit))  (sigmoid monotone)
        float pc = 1.0f / (1.0f + __expf(-cen));
        float ps = 1.0f / (1.0f + __expf(-m));

        out[(long long)NPIX * 4 + gp] = (float)mi;
        out[(long long)NPIX * 5 + gp] = sqrtf(pc * ps);
    }
}

extern "C" void kernel_launch(void* const* d_in, const int* in_sizes, int n_in,
                              void* d_out, int out_size)
{
    const float* t_ltrb = (const float*)d_in[0];
    const float* center = (const float*)d_in[1];
    const float* cls    = (const float*)d_in[2];
    float* out = (float*)d_out;

    const int total_threads = NPIX * 4;      // 4 threads per pixel
    fcos_decode_kernel<<<total_threads / TPB, TPB>>>(t_ltrb, center, cls, out);
}